// round 1
// baseline (speedup 1.0000x reference)
#include <cuda_runtime.h>
#include <cuda_bf16.h>
#include <cstring>

// Problem constants
#define BATCH 4
#define CIN   256
#define COUT  256
#define HH    64
#define WW    64
#define HW    4096   // 64*64
#define KS    3
#define NTAP  9

// Scratch: per (b, k, pixel): 4 corner indices + 4 combined weights
__device__ int4   g_idx[BATCH * NTAP * HW];
__device__ float4 g_wt [BATCH * NTAP * HW];

// ---------------------------------------------------------------------------
// Stage 1: offset conv (27 channels) + corner index/weight precompute.
// One thread per output pixel. w_off staged in shared, 8 cin per chunk,
// padded to 12 floats per (oc, cin) so tap reads are LDS.128.
// ---------------------------------------------------------------------------
__global__ __launch_bounds__(128)
void offset_kernel(const float* __restrict__ x,
                   const float* __restrict__ w_off,
                   const float* __restrict__ b_off)
{
    __shared__ float sw[27][8][12];   // [oc][cin_local][tap(9, padded 12)]

    const int t  = threadIdx.x;
    const int gp = blockIdx.x * 128 + t;          // global pixel id
    const int b  = gp >> 12;
    const int p  = gp & 4095;
    const int h  = p >> 6;
    const int w  = p & 63;

    float acc[27];
#pragma unroll
    for (int i = 0; i < 27; i++) acc[i] = 0.f;

    const float* xb = x + (size_t)b * CIN * HW;

    for (int c0 = 0; c0 < CIN; c0 += 8) {
        // stage weights
        for (int i = t; i < 27 * 8 * 9; i += 128) {
            int oc = i / 72, r = i % 72, cl = r / 9, tp = r % 9;
            sw[oc][cl][tp] = w_off[(oc * CIN + c0 + cl) * 9 + tp];
        }
        __syncthreads();

#pragma unroll 1
        for (int cl = 0; cl < 8; cl++) {
            const float* xc = xb + (size_t)(c0 + cl) * HW;
            float xv[9];
#pragma unroll
            for (int ty = 0; ty < 3; ty++) {
                const int yy = h - 1 + ty;
#pragma unroll
                for (int tx = 0; tx < 3; tx++) {
                    const int xx = w - 1 + tx;
                    const bool ok = (yy >= 0) && (yy < HH) && (xx >= 0) && (xx < WW);
                    xv[ty * 3 + tx] = ok ? __ldg(xc + yy * WW + xx) : 0.f;
                }
            }
#pragma unroll
            for (int oc = 0; oc < 27; oc++) {
                const float4* wp = reinterpret_cast<const float4*>(&sw[oc][cl][0]);
                const float4 w0 = wp[0], w1 = wp[1], w2 = wp[2];
                acc[oc] += xv[0] * w0.x + xv[1] * w0.y + xv[2] * w0.z + xv[3] * w0.w
                         + xv[4] * w1.x + xv[5] * w1.y + xv[6] * w1.z + xv[7] * w1.w
                         + xv[8] * w2.x;
            }
        }
        __syncthreads();
    }

    // Epilogue: offsets -> corner indices + weights (weight = bilinear*mask*valid)
#pragma unroll
    for (int k = 0; k < NTAP; k++) {
        const float dy = acc[2 * k]     + __ldg(b_off + 2 * k);
        const float dx = acc[2 * k + 1] + __ldg(b_off + 2 * k + 1);
        const float mz = acc[18 + k]    + __ldg(b_off + 18 + k);
        const float m  = 1.f / (1.f + expf(-mz));

        const float py = dy + (float)(h - 1 + k / 3);
        const float px = dx + (float)(w - 1 + k % 3);
        const float y0 = floorf(py);
        const float x0 = floorf(px);
        const float wy = py - y0;
        const float wx = px - x0;

        const float cy[2]  = { y0, y0 + 1.f };
        const float cx[2]  = { x0, x0 + 1.f };
        const float wyv[2] = { 1.f - wy, wy };
        const float wxv[2] = { 1.f - wx, wx };

        int   idxv[4];
        float wtv[4];
#pragma unroll
        for (int jy = 0; jy < 2; jy++) {
#pragma unroll
            for (int jx = 0; jx < 2; jx++) {
                const float yc = cy[jy], xc = cx[jx];
                const bool valid = (yc >= 0.f) && (yc <= (float)(HH - 1)) &&
                                   (xc >= 0.f) && (xc <= (float)(WW - 1));
                const int yi = (int)fminf(fmaxf(yc, 0.f), (float)(HH - 1));
                const int xi = (int)fminf(fmaxf(xc, 0.f), (float)(WW - 1));
                const int j = jy * 2 + jx;
                idxv[j] = yi * WW + xi;
                wtv[j]  = valid ? (wyv[jy] * wxv[jx] * m) : 0.f;
            }
        }
        const int o = (b * NTAP + k) * HW + p;
        g_idx[o] = make_int4(idxv[0], idxv[1], idxv[2], idxv[3]);
        g_wt[o]  = make_float4(wtv[0], wtv[1], wtv[2], wtv[3]);
    }
}

// ---------------------------------------------------------------------------
// Stage 2: implicit GEMM.
// out[b, o, p] = sum_{c,k} w_conv[o, c*9+k] * ( sum_j wt[b,k,p,j]*x[b,c,idx[b,k,p,j]] )
// M = 16384 (pixels), N = 256 (cout), K = 2304 (c*9+k).
// Tile: BM=128, BN=128, BK=36 (4 cin x 9 taps). 256 threads, 8x8 per thread.
// Accumulation in packed f32x2 (FFMA2) -> 128 FMA/cyc/SM ceiling.
// ---------------------------------------------------------------------------
__device__ __forceinline__ void fma2(unsigned long long& d,
                                     unsigned long long a,
                                     unsigned long long bcol)
{
    asm("fma.rn.f32x2 %0, %1, %2, %0;" : "+l"(d) : "l"(a), "l"(bcol));
}

__global__ __launch_bounds__(256)
void gemm_kernel(const float* __restrict__ x,
                 const float* __restrict__ w_conv,
                 float* __restrict__ out)
{
    __shared__ float sA[36][128];
    __shared__ float sB[36][132];   // padded row (132) to kill store bank conflicts

    const int t  = threadIdx.x;
    const int mt = blockIdx.x;      // 0..127, 32 M-tiles per image
    const int nt = blockIdx.y;      // 0..1
    const int b  = mt >> 5;
    const int p0 = (mt & 31) * 128; // pixel base within image
    const int n0 = nt * 128;

    const float* xb = x + (size_t)b * CIN * HW;

    // A-build assignment: pixel = t&127, c_local pair selected by t>>7
    const int ap = t & 127;
    const int ah = t >> 7;          // 0/1 -> c_local {0,1} or {2,3}

    // Compute assignment: M rows (t%16)*2 + 32*i (i=0..3, as f32x2 pairs),
    // N cols (t/16)*8 .. +8
    const int mrow = (t & 15) * 2;
    const int nb   = (t >> 4) * 8;

    unsigned long long acc[4][8];
#pragma unroll
    for (int i = 0; i < 4; i++)
#pragma unroll
        for (int j = 0; j < 8; j++) acc[i][j] = 0ULL;

    for (int chunk = 0; chunk < 64; chunk++) {
        const int c0 = chunk * 4;

        // ---- load B tile: w_conv[n0+o][c0*9 .. c0*9+36) ----
        for (int i = t; i < 1152; i += 256) {
            const int o = i / 9, v = i % 9;
            const float4 wv = __ldg(reinterpret_cast<const float4*>(
                w_conv + (size_t)(n0 + o) * (CIN * NTAP) + c0 * 9) + v);
            const int kk = v * 4;
            sB[kk    ][o] = wv.x;
            sB[kk + 1][o] = wv.y;
            sB[kk + 2][o] = wv.z;
            sB[kk + 3][o] = wv.w;
        }

        // ---- build A tile: bilinear gather + mask ----
#pragma unroll
        for (int cc = 0; cc < 2; cc++) {
            const int cl = ah * 2 + cc;
            const float* xc = xb + (size_t)(c0 + cl) * HW;
#pragma unroll
            for (int k = 0; k < NTAP; k++) {
                const int off = (b * NTAP + k) * HW + p0 + ap;
                const int4   id = g_idx[off];
                const float4 wt = g_wt[off];
                const float a = wt.x * __ldg(xc + id.x)
                              + wt.y * __ldg(xc + id.y)
                              + wt.z * __ldg(xc + id.z)
                              + wt.w * __ldg(xc + id.w);
                sA[cl * 9 + k][ap] = a;
            }
        }
        __syncthreads();

        // ---- FFMA2 mainloop ----
#pragma unroll
        for (int kk = 0; kk < 36; kk++) {
            unsigned long long av[4];
#pragma unroll
            for (int i = 0; i < 4; i++)
                av[i] = *reinterpret_cast<const unsigned long long*>(
                            &sA[kk][mrow + 32 * i]);

            float bv[8];
            *reinterpret_cast<float4*>(&bv[0]) =
                *reinterpret_cast<const float4*>(&sB[kk][nb]);
            *reinterpret_cast<float4*>(&bv[4]) =
                *reinterpret_cast<const float4*>(&sB[kk][nb + 4]);

#pragma unroll
            for (int j = 0; j < 8; j++) {
                unsigned long long bb;
                asm("mov.b64 %0, {%1, %1};" : "=l"(bb) : "f"(bv[j]));
#pragma unroll
                for (int i = 0; i < 4; i++) fma2(acc[i][j], av[i], bb);
            }
        }
        __syncthreads();
    }

    // ---- epilogue ----
    float* ob = out + ((size_t)(b * COUT + n0)) * HW + p0;
#pragma unroll
    for (int j = 0; j < 8; j++) {
#pragma unroll
        for (int i = 0; i < 4; i++) {
            float2 v;
            unsigned long long u = acc[i][j];
            asm("mov.b64 {%0, %1}, %2;" : "=f"(v.x), "=f"(v.y) : "l"(u));
            *reinterpret_cast<float2*>(&ob[(size_t)(nb + j) * HW + mrow + 32 * i]) = v;
        }
    }
}

// ---------------------------------------------------------------------------
extern "C" void kernel_launch(void* const* d_in, const int* in_sizes, int n_in,
                              void* d_out, int out_size)
{
    (void)in_sizes; (void)n_in; (void)out_size;
    const float* x      = (const float*)d_in[0];
    const float* w_off  = (const float*)d_in[1];
    const float* b_off  = (const float*)d_in[2];
    const float* w_conv = (const float*)d_in[3];
    float* out = (float*)d_out;

    offset_kernel<<<BATCH * HW / 128, 128>>>(x, w_off, b_off);
    gemm_kernel<<<dim3(128, 2), 256>>>(x, w_conv, out);
}

// round 3
// speedup vs baseline: 1.8680x; 1.8680x over previous
#include <cuda_runtime.h>
#include <cuda_bf16.h>
#include <cstdint>

// Problem constants
#define BATCH 4
#define CIN   256
#define COUT  256
#define HH    64
#define WW    64
#define HW    4096
#define NTAP  9
#define KTOT  2304        // tap-major: k = tap*256 + c
#define NCHUNK 36         // 9 taps * 4 chunks of 64 channels

// ---------------- scratch ----------------
__device__ int4   g_idx[BATCH * NTAP * HW];
__device__ float4 g_wt [BATCH * NTAP * HW];
__device__ __nv_bfloat16 g_bh[COUT * KTOT];   // [n][k], k = tap*256 + c
__device__ __nv_bfloat16 g_bl[COUT * KTOT];

// ---------------- helpers ----------------
__device__ __forceinline__ uint32_t smem_u32(const void* p) {
    uint32_t a;
    asm("{ .reg .u64 t; cvta.to.shared.u64 t, %1; cvt.u32.u64 %0, t; }" : "=r"(a) : "l"(p));
    return a;
}

__device__ __forceinline__ void ldm_x4(uint32_t* r, uint32_t addr) {
    asm volatile("ldmatrix.sync.aligned.m8n8.x4.shared.b16 {%0,%1,%2,%3}, [%4];"
                 : "=r"(r[0]), "=r"(r[1]), "=r"(r[2]), "=r"(r[3]) : "r"(addr));
}

__device__ __forceinline__ void mma_bf16(float* c, const uint32_t* a, const uint32_t* b) {
    asm volatile(
        "mma.sync.aligned.m16n8k16.row.col.f32.bf16.bf16.f32 "
        "{%0,%1,%2,%3}, {%4,%5,%6,%7}, {%8,%9}, {%0,%1,%2,%3};"
        : "+f"(c[0]), "+f"(c[1]), "+f"(c[2]), "+f"(c[3])
        : "r"(a[0]), "r"(a[1]), "r"(a[2]), "r"(a[3]), "r"(b[0]), "r"(b[1]));
}

// ---------------------------------------------------------------------------
// Stage 0: prepack w_conv -> tap-major bf16 hi/lo, layout [n][tap*256+c]
// ---------------------------------------------------------------------------
__global__ __launch_bounds__(256)
void prepack_kernel(const float* __restrict__ w_conv)
{
    const int i = blockIdx.x * 256 + threadIdx.x;
    if (i >= COUT * KTOT) return;
    const int n = i / KTOT, k = i % KTOT;
    const int tap = k >> 8, c = k & 255;
    const float w = w_conv[(n * CIN + c) * 9 + tap];
    const __nv_bfloat16 h = __float2bfloat16_rn(w);
    g_bh[i] = h;
    g_bl[i] = __float2bfloat16_rn(w - __bfloat162float(h));
}

// ---------------------------------------------------------------------------
// Stage 1: offset conv (27 ch) + corner index/weight precompute.
// ---------------------------------------------------------------------------
__global__ __launch_bounds__(128)
void offset_kernel(const float* __restrict__ x,
                   const float* __restrict__ w_off,
                   const float* __restrict__ b_off)
{
    __shared__ float sw[27][8][12];

    const int t  = threadIdx.x;
    const int gp = blockIdx.x * 128 + t;
    const int b  = gp >> 12;
    const int p  = gp & 4095;
    const int h  = p >> 6;
    const int w  = p & 63;

    float acc[27];
#pragma unroll
    for (int i = 0; i < 27; i++) acc[i] = 0.f;

    const float* xb = x + (size_t)b * CIN * HW;

    for (int c0 = 0; c0 < CIN; c0 += 8) {
        for (int i = t; i < 27 * 8 * 9; i += 128) {
            int oc = i / 72, r = i % 72, cl = r / 9, tp = r % 9;
            sw[oc][cl][tp] = w_off[(oc * CIN + c0 + cl) * 9 + tp];
        }
        __syncthreads();

#pragma unroll 1
        for (int cl = 0; cl < 8; cl++) {
            const float* xc = xb + (size_t)(c0 + cl) * HW;
            float xv[9];
#pragma unroll
            for (int ty = 0; ty < 3; ty++) {
                const int yy = h - 1 + ty;
#pragma unroll
                for (int tx = 0; tx < 3; tx++) {
                    const int xx = w - 1 + tx;
                    const bool ok = (yy >= 0) && (yy < HH) && (xx >= 0) && (xx < WW);
                    xv[ty * 3 + tx] = ok ? __ldg(xc + yy * WW + xx) : 0.f;
                }
            }
#pragma unroll
            for (int oc = 0; oc < 27; oc++) {
                const float4* wp = reinterpret_cast<const float4*>(&sw[oc][cl][0]);
                const float4 w0 = wp[0], w1 = wp[1], w2 = wp[2];
                acc[oc] += xv[0] * w0.x + xv[1] * w0.y + xv[2] * w0.z + xv[3] * w0.w
                         + xv[4] * w1.x + xv[5] * w1.y + xv[6] * w1.z + xv[7] * w1.w
                         + xv[8] * w2.x;
            }
        }
        __syncthreads();
    }

#pragma unroll
    for (int k = 0; k < NTAP; k++) {
        const float dy = acc[2 * k]     + __ldg(b_off + 2 * k);
        const float dx = acc[2 * k + 1] + __ldg(b_off + 2 * k + 1);
        const float mz = acc[18 + k]    + __ldg(b_off + 18 + k);
        const float m  = 1.f / (1.f + expf(-mz));

        const float py = dy + (float)(h - 1 + k / 3);
        const float px = dx + (float)(w - 1 + k % 3);
        const float y0 = floorf(py);
        const float x0 = floorf(px);
        const float wy = py - y0;
        const float wx = px - x0;

        const float cy[2]  = { y0, y0 + 1.f };
        const float cx[2]  = { x0, x0 + 1.f };
        const float wyv[2] = { 1.f - wy, wy };
        const float wxv[2] = { 1.f - wx, wx };

        int   idxv[4];
        float wtv[4];
#pragma unroll
        for (int jy = 0; jy < 2; jy++) {
#pragma unroll
            for (int jx = 0; jx < 2; jx++) {
                const float yc = cy[jy], xc = cx[jx];
                const bool valid = (yc >= 0.f) && (yc <= (float)(HH - 1)) &&
                                   (xc >= 0.f) && (xc <= (float)(WW - 1));
                const int yi = (int)fminf(fmaxf(yc, 0.f), (float)(HH - 1));
                const int xi = (int)fminf(fmaxf(xc, 0.f), (float)(WW - 1));
                const int j = jy * 2 + jx;
                idxv[j] = yi * WW + xi;
                wtv[j]  = valid ? (wyv[jy] * wxv[jx] * m) : 0.f;
            }
        }
        const int o = (b * NTAP + k) * HW + p;
        g_idx[o] = make_int4(idxv[0], idxv[1], idxv[2], idxv[3]);
        g_wt[o]  = make_float4(wtv[0], wtv[1], wtv[2], wtv[3]);
    }
}

// ---------------------------------------------------------------------------
// Stage 2: implicit GEMM via mma.sync bf16 (hi/lo x3-term fp32 emulation).
// Per CTA: 128 pixels x 256 couts. 512 threads, 16 warps (2m x 8n), warp
// tile 64x32. K loop: 36 chunks (one tap x 64 channels), double-buffered.
// SMEM rows padded to 72 bf16 (144 B) -> conflict-free ldmatrix.
// ---------------------------------------------------------------------------
#define ROWB   144            // bytes per smem row (72 bf16)
#define SM_AHI 0
#define SM_ALO (128 * ROWB)                   // 18432
#define SM_BHI (2 * 128 * ROWB)               // 36864
#define SM_BLO (SM_BHI + 256 * ROWB)          // 73728
#define BUF_BYTES (SM_BLO + 256 * ROWB)       // 110592
#define SMEM_TOTAL (2 * BUF_BYTES)            // 221184

__global__ __launch_bounds__(512, 1)
void mma_kernel(const float* __restrict__ x, float* __restrict__ out)
{
    extern __shared__ char smem[];
    const uint32_t sb = smem_u32(smem);
    const int t    = threadIdx.x;
    const int lane = t & 31;
    const int wid  = t >> 5;
    const int b    = blockIdx.x >> 5;
    const int p0   = (blockIdx.x & 31) * 128;

    const float* xb = x + (size_t)b * CIN * HW;

    // A-build: pixel = t&127, channel quarter = t>>7 (16 channels each)
    const int am = t & 127;
    const int aq = t >> 7;

    // compute assignment
    const int mw = wid & 1;        // 0/1 -> 64 pixels each
    const int nw = wid >> 1;       // 0..7 -> 32 couts each

    float acc[4][4][4];
#pragma unroll
    for (int mi = 0; mi < 4; mi++)
#pragma unroll
        for (int ni = 0; ni < 4; ni++)
#pragma unroll
            for (int j = 0; j < 4; j++) acc[mi][ni][j] = 0.f;

    // ldmatrix lane addressing (byte offsets, before mi/np/s terms)
    const uint32_t a_row  = (uint32_t)(mw * 64 + (lane & 15));
    const uint32_t a_colb = (uint32_t)((lane >> 4) * 16);
    const uint32_t b_row  = (uint32_t)(nw * 32 + (lane & 7) + ((lane >> 4) << 3));
    const uint32_t b_colb = (uint32_t)(((lane >> 3) & 1) * 16);

    // ---- builders ----
    auto build = [&](int chunk, uint32_t base) {
        const int tap = chunk >> 2;
        const int c0  = (chunk & 3) * 64;
        // A tile: gather + bilinear + hi/lo split
        {
            const int off = (b * NTAP + tap) * HW + p0 + am;
            const int4   id = g_idx[off];
            const float4 wt = g_wt[off];
            const float* xc = xb + (size_t)(c0 + aq * 16) * HW;
#pragma unroll
            for (int cp = 0; cp < 8; cp++) {
                const float* xp0 = xc + (size_t)(2 * cp) * HW;
                const float* xp1 = xp0 + HW;
                const float v0 = wt.x * __ldg(xp0 + id.x) + wt.y * __ldg(xp0 + id.y)
                               + wt.z * __ldg(xp0 + id.z) + wt.w * __ldg(xp0 + id.w);
                const float v1 = wt.x * __ldg(xp1 + id.x) + wt.y * __ldg(xp1 + id.y)
                               + wt.z * __ldg(xp1 + id.z) + wt.w * __ldg(xp1 + id.w);
                const __nv_bfloat16 h0 = __float2bfloat16_rn(v0);
                const __nv_bfloat16 h1 = __float2bfloat16_rn(v1);
                const __nv_bfloat16 l0 = __float2bfloat16_rn(v0 - __bfloat162float(h0));
                const __nv_bfloat16 l1 = __float2bfloat16_rn(v1 - __bfloat162float(h1));
                const uint32_t hi2 = (uint32_t)__bfloat16_as_ushort(h0)
                                   | ((uint32_t)__bfloat16_as_ushort(h1) << 16);
                const uint32_t lo2 = (uint32_t)__bfloat16_as_ushort(l0)
                                   | ((uint32_t)__bfloat16_as_ushort(l1) << 16);
                const uint32_t bo = (uint32_t)(am * ROWB + (aq * 16 + 2 * cp) * 2);
                asm volatile("st.shared.b32 [%0], %1;" :: "r"(base + SM_AHI + bo), "r"(hi2) : "memory");
                asm volatile("st.shared.b32 [%0], %1;" :: "r"(base + SM_ALO + bo), "r"(lo2) : "memory");
            }
        }
        // B tile: 256 rows x 64 bf16 (hi/lo), coalesced uint4
        {
#pragma unroll
            for (int q2 = 0; q2 < 4; q2++) {
                const int v  = t + 512 * q2;      // 0..2047
                const int n  = v >> 3, vw = v & 7;
                const size_t gofs = (size_t)n * KTOT + tap * 256 + c0 + vw * 8;
                const uint4 hv = *reinterpret_cast<const uint4*>(g_bh + gofs);
                const uint4 lv = *reinterpret_cast<const uint4*>(g_bl + gofs);
                const uint32_t bo = (uint32_t)(n * ROWB + vw * 16);
                asm volatile("st.shared.v4.b32 [%0], {%1,%2,%3,%4};"
                             :: "r"(base + SM_BHI + bo), "r"(hv.x), "r"(hv.y), "r"(hv.z), "r"(hv.w) : "memory");
                asm volatile("st.shared.v4.b32 [%0], {%1,%2,%3,%4};"
                             :: "r"(base + SM_BLO + bo), "r"(lv.x), "r"(lv.y), "r"(lv.z), "r"(lv.w) : "memory");
            }
        }
    };

    auto compute = [&](uint32_t base) {
        const uint32_t Ah = base + SM_AHI, Al = base + SM_ALO;
        const uint32_t Bh = base + SM_BHI, Bl = base + SM_BLO;
        // pass 1: Ah*Bh + Ah*Bl
#pragma unroll
        for (int s = 0; s < 4; s++) {
            uint32_t af[4][4];
#pragma unroll
            for (int mi = 0; mi < 4; mi++)
                ldm_x4(af[mi], Ah + (a_row + mi * 16) * ROWB + a_colb + s * 32);
            uint32_t bhf[4][2], blf[4][2];
#pragma unroll
            for (int np = 0; np < 2; np++) {
                uint32_t r[4];
                ldm_x4(r, Bh + (b_row + np * 16) * ROWB + b_colb + s * 32);
                bhf[np * 2][0] = r[0]; bhf[np * 2][1] = r[1];
                bhf[np * 2 + 1][0] = r[2]; bhf[np * 2 + 1][1] = r[3];
                ldm_x4(r, Bl + (b_row + np * 16) * ROWB + b_colb + s * 32);
                blf[np * 2][0] = r[0]; blf[np * 2][1] = r[1];
                blf[np * 2 + 1][0] = r[2]; blf[np * 2 + 1][1] = r[3];
            }
#pragma unroll
            for (int mi = 0; mi < 4; mi++)
#pragma unroll
                for (int ni = 0; ni < 4; ni++) {
                    mma_bf16(acc[mi][ni], af[mi], bhf[ni]);
                    mma_bf16(acc[mi][ni], af[mi], blf[ni]);
                }
        }
        // pass 2: Al*Bh
#pragma unroll
        for (int s = 0; s < 4; s++) {
            uint32_t af[4][4];
#pragma unroll
            for (int mi = 0; mi < 4; mi++)
                ldm_x4(af[mi], Al + (a_row + mi * 16) * ROWB + a_colb + s * 32);
            uint32_t bhf[4][2];
#pragma unroll
            for (int np = 0; np < 2; np++) {
                uint32_t r[4];
                ldm_x4(r, Bh + (b_row + np * 16) * ROWB + b_colb + s * 32);
                bhf[np * 2][0] = r[0]; bhf[np * 2][1] = r[1];
                bhf[np * 2 + 1][0] = r[2]; bhf[np * 2 + 1][1] = r[3];
            }
#pragma unroll
            for (int mi = 0; mi < 4; mi++)
#pragma unroll
                for (int ni = 0; ni < 4; ni++)
                    mma_bf16(acc[mi][ni], af[mi], bhf[ni]);
        }
    };

    // ---- pipelined K loop ----
    build(0, sb);
    __syncthreads();
    for (int chunk = 0; chunk < NCHUNK; chunk++) {
        const uint32_t cur = sb + (uint32_t)(chunk & 1) * BUF_BYTES;
        if (chunk + 1 < NCHUNK)
            build(chunk + 1, sb + (uint32_t)((chunk + 1) & 1) * BUF_BYTES);
        compute(cur);
        __syncthreads();
    }

    // ---- epilogue ----
    float* ob = out + (size_t)b * COUT * HW + p0;
    const int mbase = mw * 64 + (lane >> 2);
    const int nbase = nw * 32 + (lane & 3) * 2;
#pragma unroll
    for (int mi = 0; mi < 4; mi++) {
#pragma unroll
        for (int ni = 0; ni < 4; ni++) {
            const int m = mbase + mi * 16;
            const int n = nbase + ni * 8;
            ob[(size_t)n * HW + m]           = acc[mi][ni][0];
            ob[(size_t)(n + 1) * HW + m]     = acc[mi][ni][1];
            ob[(size_t)n * HW + m + 8]       = acc[mi][ni][2];
            ob[(size_t)(n + 1) * HW + m + 8] = acc[mi][ni][3];
        }
    }
}

// ---------------------------------------------------------------------------
extern "C" void kernel_launch(void* const* d_in, const int* in_sizes, int n_in,
                              void* d_out, int out_size)
{
    (void)in_sizes; (void)n_in; (void)out_size;
    const float* x      = (const float*)d_in[0];
    const float* w_off  = (const float*)d_in[1];
    const float* b_off  = (const float*)d_in[2];
    const float* w_conv = (const float*)d_in[3];
    float* out = (float*)d_out;

    cudaFuncSetAttribute(mma_kernel,
                         cudaFuncAttributeMaxDynamicSharedMemorySize, SMEM_TOTAL);

    prepack_kernel<<<(COUT * KTOT + 255) / 256, 256>>>(w_conv);
    offset_kernel<<<BATCH * HW / 128, 128>>>(x, w_off, b_off);
    mma_kernel<<<128, 512, SMEM_TOTAL>>>(x, out);
}

// round 4
// speedup vs baseline: 3.1489x; 1.6857x over previous
#include <cuda_runtime.h>
#include <cuda_bf16.h>
#include <cstdint>

// Problem constants
#define BATCH 4
#define CIN   256
#define COUT  256
#define HH    64
#define WW    64
#define HW    4096
#define NTAP  9
#define KTOT  2304        // tap-major: k = tap*256 + c
#define NCHUNK 36         // 9 taps * 4 chunks of 64 channels

// ---------------- scratch ----------------
__device__ int4   g_idx[BATCH * NTAP * HW];
__device__ float4 g_wt [BATCH * NTAP * HW];
__device__ __nv_bfloat16 g_bh[COUT * KTOT];   // w_conv  [n][k], k = tap*256 + c
__device__ __nv_bfloat16 g_bl[COUT * KTOT];
__device__ __nv_bfloat16 g_oh[32 * KTOT];     // w_off   [n(27->32)][k]
__device__ __nv_bfloat16 g_ol[32 * KTOT];

// ---------------- helpers ----------------
__device__ __forceinline__ uint32_t smem_u32(const void* p) {
    uint32_t a;
    asm("{ .reg .u64 t; cvta.to.shared.u64 t, %1; cvt.u32.u64 %0, t; }" : "=r"(a) : "l"(p));
    return a;
}
__device__ __forceinline__ void ldm_x4(uint32_t* r, uint32_t addr) {
    asm volatile("ldmatrix.sync.aligned.m8n8.x4.shared.b16 {%0,%1,%2,%3}, [%4];"
                 : "=r"(r[0]), "=r"(r[1]), "=r"(r[2]), "=r"(r[3]) : "r"(addr));
}
__device__ __forceinline__ void mma_bf16(float* c, const uint32_t* a, const uint32_t* b) {
    asm volatile(
        "mma.sync.aligned.m16n8k16.row.col.f32.bf16.bf16.f32 "
        "{%0,%1,%2,%3}, {%4,%5,%6,%7}, {%8,%9}, {%0,%1,%2,%3};"
        : "+f"(c[0]), "+f"(c[1]), "+f"(c[2]), "+f"(c[3])
        : "r"(a[0]), "r"(a[1]), "r"(a[2]), "r"(a[3]), "r"(b[0]), "r"(b[1]));
}
__device__ __forceinline__ void cpasync16(uint32_t dst, const void* src) {
    asm volatile("cp.async.cg.shared.global [%0], [%1], 16;" :: "r"(dst), "l"(src));
}
#define CP_COMMIT() asm volatile("cp.async.commit_group;")
#define CP_WAIT0()  asm volatile("cp.async.wait_group 0;" ::: "memory")

__device__ __forceinline__ uint32_t pack_bf16x2(float v0, float v1,
                                                uint32_t& lo_out) {
    const __nv_bfloat16 h0 = __float2bfloat16_rn(v0);
    const __nv_bfloat16 h1 = __float2bfloat16_rn(v1);
    const __nv_bfloat16 l0 = __float2bfloat16_rn(v0 - __bfloat162float(h0));
    const __nv_bfloat16 l1 = __float2bfloat16_rn(v1 - __bfloat162float(h1));
    lo_out = (uint32_t)__bfloat16_as_ushort(l0) | ((uint32_t)__bfloat16_as_ushort(l1) << 16);
    return (uint32_t)__bfloat16_as_ushort(h0) | ((uint32_t)__bfloat16_as_ushort(h1) << 16);
}

// ---------------------------------------------------------------------------
// Stage 0: prepack w_conv + w_off -> tap-major bf16 hi/lo
// ---------------------------------------------------------------------------
__global__ __launch_bounds__(256)
void prepack_kernel(const float* __restrict__ w_conv,
                    const float* __restrict__ w_off)
{
    const int i = blockIdx.x * 256 + threadIdx.x;
    if (i < COUT * KTOT) {
        const int n = i / KTOT, k = i % KTOT;
        const int tap = k >> 8, c = k & 255;
        const float w = w_conv[(n * CIN + c) * 9 + tap];
        const __nv_bfloat16 h = __float2bfloat16_rn(w);
        g_bh[i] = h;
        g_bl[i] = __float2bfloat16_rn(w - __bfloat162float(h));
    } else if (i < (COUT + 32) * KTOT) {
        const int j = i - COUT * KTOT;
        const int n = j / KTOT, k = j % KTOT;
        const int tap = k >> 8, c = k & 255;
        const float w = (n < 27) ? w_off[(n * CIN + c) * 9 + tap] : 0.f;
        const __nv_bfloat16 h = __float2bfloat16_rn(w);
        g_oh[j] = h;
        g_ol[j] = __float2bfloat16_rn(w - __bfloat162float(h));
    }
}

// ---------------------------------------------------------------------------
// Stage 1: offset conv on tensor cores (M=128/CTA, N=32, K=2304) + epilogue
// producing bilinear corner indices/weights.
// ---------------------------------------------------------------------------
#define OROWB 144
#define OS_AHI 0
#define OS_ALO (128 * OROWB)                  // 18432
#define OS_BHI (2 * 128 * OROWB)              // 36864
#define OS_BLO (OS_BHI + 32 * OROWB)          // 41472
#define OBUF   (OS_BLO + 32 * OROWB)          // 46080
#define OS_ACC (2 * OBUF)                     // 92160
#define OSMEM_TOTAL (OS_ACC + 128 * 33 * 4)   // 109056

__global__ __launch_bounds__(256, 1)
void offset_mma_kernel(const float* __restrict__ x,
                       const float* __restrict__ b_off)
{
    extern __shared__ char smem[];
    const uint32_t sb = smem_u32(smem);
    const int t    = threadIdx.x;
    const int lane = t & 31;
    const int wid  = t >> 5;
    const int b    = blockIdx.x >> 5;
    const int p0   = (blockIdx.x & 31) * 128;

    const float* xb = x + (size_t)b * CIN * HW;

    // A-build: pixel = t&127, channel half = t>>7 (32 channels)
    const int am = t & 127;
    const int ah = t >> 7;
    const int ph = (p0 + am) >> 6;
    const int pw = (p0 + am) & 63;

    // compute assignment: warp wid -> rows wid*16..+16, all 32 n
    const uint32_t a_row  = (uint32_t)(wid * 16 + (lane & 15));
    const uint32_t a_colb = (uint32_t)((lane >> 4) * 16);
    const uint32_t b_row  = (uint32_t)((lane & 7) + ((lane >> 4) << 3));
    const uint32_t b_colb = (uint32_t)(((lane >> 3) & 1) * 16);

    float acc[4][4];
#pragma unroll
    for (int ni = 0; ni < 4; ni++)
#pragma unroll
        for (int j = 0; j < 4; j++) acc[ni][j] = 0.f;

    auto build_a = [&](int chunk, uint32_t base) {
        const int tap = chunk >> 2;
        const int c0  = (chunk & 3) * 64;
        const int yy = ph - 1 + tap / 3;
        const int xx = pw - 1 + tap % 3;
        const bool ok = (yy >= 0) && (yy < HH) && (xx >= 0) && (xx < WW);
        const int sidx = ok ? (yy * WW + xx) : 0;
        const float* xc = xb + (size_t)(c0 + ah * 32) * HW + sidx;
#pragma unroll
        for (int jj = 0; jj < 16; jj++) {
            const float v0 = ok ? __ldg(xc + (size_t)(2 * jj) * HW) : 0.f;
            const float v1 = ok ? __ldg(xc + (size_t)(2 * jj + 1) * HW) : 0.f;
            uint32_t lo2, hi2 = pack_bf16x2(v0, v1, lo2);
            const uint32_t bo = (uint32_t)(am * OROWB + (ah * 32 + 2 * jj) * 2);
            asm volatile("st.shared.b32 [%0], %1;" :: "r"(base + OS_AHI + bo), "r"(hi2) : "memory");
            asm volatile("st.shared.b32 [%0], %1;" :: "r"(base + OS_ALO + bo), "r"(lo2) : "memory");
        }
    };
    auto build_b = [&](int chunk, uint32_t base) {
        const int tap = chunk >> 2;
        const int c0  = (chunk & 3) * 64;
        const int n = t >> 3, vw = t & 7;   // 256 threads cover 32 n x 8 vec
        const size_t gofs = (size_t)n * KTOT + tap * 256 + c0 + vw * 8;
        const uint32_t bo = (uint32_t)(n * OROWB + vw * 16);
        cpasync16(base + OS_BHI + bo, g_oh + gofs);
        cpasync16(base + OS_BLO + bo, g_ol + gofs);
        CP_COMMIT();
    };
    auto compute = [&](uint32_t base) {
        const uint32_t Ah = base + OS_AHI, Al = base + OS_ALO;
        const uint32_t Bh = base + OS_BHI, Bl = base + OS_BLO;
#pragma unroll
        for (int s = 0; s < 4; s++) {
            uint32_t af[4];
            ldm_x4(af, Ah + a_row * OROWB + a_colb + s * 32);
            uint32_t bhf[4][2], blf[4][2];
#pragma unroll
            for (int np = 0; np < 2; np++) {
                uint32_t r[4];
                ldm_x4(r, Bh + (b_row + np * 16) * OROWB + b_colb + s * 32);
                bhf[np * 2][0] = r[0]; bhf[np * 2][1] = r[1];
                bhf[np * 2 + 1][0] = r[2]; bhf[np * 2 + 1][1] = r[3];
                ldm_x4(r, Bl + (b_row + np * 16) * OROWB + b_colb + s * 32);
                blf[np * 2][0] = r[0]; blf[np * 2][1] = r[1];
                blf[np * 2 + 1][0] = r[2]; blf[np * 2 + 1][1] = r[3];
            }
#pragma unroll
            for (int ni = 0; ni < 4; ni++) {
                mma_bf16(acc[ni], af, bhf[ni]);
                mma_bf16(acc[ni], af, blf[ni]);
            }
        }
#pragma unroll
        for (int s = 0; s < 4; s++) {
            uint32_t af[4];
            ldm_x4(af, Al + a_row * OROWB + a_colb + s * 32);
            uint32_t bhf[4][2];
#pragma unroll
            for (int np = 0; np < 2; np++) {
                uint32_t r[4];
                ldm_x4(r, Bh + (b_row + np * 16) * OROWB + b_colb + s * 32);
                bhf[np * 2][0] = r[0]; bhf[np * 2][1] = r[1];
                bhf[np * 2 + 1][0] = r[2]; bhf[np * 2 + 1][1] = r[3];
            }
#pragma unroll
            for (int ni = 0; ni < 4; ni++)
                mma_bf16(acc[ni], af, bhf[ni]);
        }
    };

    build_b(0, sb);
    build_a(0, sb);
    CP_WAIT0();
    __syncthreads();
    for (int chunk = 0; chunk < NCHUNK; chunk++) {
        const uint32_t cur = sb + (uint32_t)(chunk & 1) * OBUF;
        if (chunk + 1 < NCHUNK) {
            const uint32_t nxt = sb + (uint32_t)((chunk + 1) & 1) * OBUF;
            build_b(chunk + 1, nxt);
            build_a(chunk + 1, nxt);
        }
        compute(cur);
        CP_WAIT0();
        __syncthreads();
    }

    // stash acc to smem so each thread can read a whole pixel row
    float* sacc = reinterpret_cast<float*>(smem + OS_ACC);
    const int mb = wid * 16 + (lane >> 2);
    const int nb = (lane & 3) * 2;
#pragma unroll
    for (int ni = 0; ni < 4; ni++) {
        const int n = nb + ni * 8;
        sacc[mb * 33 + n]           = acc[ni][0];
        sacc[mb * 33 + n + 1]       = acc[ni][1];
        sacc[(mb + 8) * 33 + n]     = acc[ni][2];
        sacc[(mb + 8) * 33 + n + 1] = acc[ni][3];
    }
    __syncthreads();

    if (t < 128) {
        const int p = p0 + t;
        const int h = p >> 6, w = p & 63;
        const float* row = sacc + t * 33;
#pragma unroll
        for (int k = 0; k < NTAP; k++) {
            const float dy = row[2 * k]     + __ldg(b_off + 2 * k);
            const float dx = row[2 * k + 1] + __ldg(b_off + 2 * k + 1);
            const float mz = row[18 + k]    + __ldg(b_off + 18 + k);
            const float m  = 1.f / (1.f + expf(-mz));

            const float py = dy + (float)(h - 1 + k / 3);
            const float px = dx + (float)(w - 1 + k % 3);
            const float y0 = floorf(py);
            const float x0 = floorf(px);
            const float wy = py - y0;
            const float wx = px - x0;

            const float cy[2]  = { y0, y0 + 1.f };
            const float cx[2]  = { x0, x0 + 1.f };
            const float wyv[2] = { 1.f - wy, wy };
            const float wxv[2] = { 1.f - wx, wx };

            int   idxv[4];
            float wtv[4];
#pragma unroll
            for (int jy = 0; jy < 2; jy++) {
#pragma unroll
                for (int jx = 0; jx < 2; jx++) {
                    const float yc = cy[jy], xc = cx[jx];
                    const bool valid = (yc >= 0.f) && (yc <= (float)(HH - 1)) &&
                                       (xc >= 0.f) && (xc <= (float)(WW - 1));
                    const int yi = (int)fminf(fmaxf(yc, 0.f), (float)(HH - 1));
                    const int xi = (int)fminf(fmaxf(xc, 0.f), (float)(WW - 1));
                    const int j = jy * 2 + jx;
                    idxv[j] = yi * WW + xi;
                    wtv[j]  = valid ? (wyv[jy] * wxv[jx] * m) : 0.f;
                }
            }
            const int o = (b * NTAP + k) * HW + p;
            g_idx[o] = make_int4(idxv[0], idxv[1], idxv[2], idxv[3]);
            g_wt[o]  = make_float4(wtv[0], wtv[1], wtv[2], wtv[3]);
        }
    }
}

// ---------------------------------------------------------------------------
// Stage 2: implicit GEMM via mma.sync bf16 (hi/lo x3-term fp32 emulation).
// 128 pixels x 256 couts per CTA, 512 threads (16 warps, 2m x 8n).
// A-gather for NEXT chunk interleaved with HMMA of CURRENT chunk (8 groups
// of 8 LDG, each covered by one mma s-step); B via cp.async.
// ---------------------------------------------------------------------------
#define ROWB   144
#define SM_AHI 0
#define SM_ALO (128 * ROWB)
#define SM_BHI (2 * 128 * ROWB)
#define SM_BLO (SM_BHI + 256 * ROWB)
#define BUF_BYTES (SM_BLO + 256 * ROWB)       // 110592
#define SMEM_TOTAL (2 * BUF_BYTES)            // 221184

__global__ __launch_bounds__(512, 1)
void mma_kernel(const float* __restrict__ x, float* __restrict__ out)
{
    extern __shared__ char smem[];
    const uint32_t sb = smem_u32(smem);
    const int t    = threadIdx.x;
    const int lane = t & 31;
    const int wid  = t >> 5;
    const int b    = blockIdx.x >> 5;
    const int p0   = (blockIdx.x & 31) * 128;

    const float* xb = x + (size_t)b * CIN * HW;

    const int am = t & 127;   // pixel
    const int aq = t >> 7;    // channel quarter (16 ch)

    const int mw = wid & 1;
    const int nw = wid >> 1;

    float acc[4][4][4];
#pragma unroll
    for (int mi = 0; mi < 4; mi++)
#pragma unroll
        for (int ni = 0; ni < 4; ni++)
#pragma unroll
            for (int j = 0; j < 4; j++) acc[mi][ni][j] = 0.f;

    const uint32_t a_row  = (uint32_t)(mw * 64 + (lane & 15));
    const uint32_t a_colb = (uint32_t)((lane >> 4) * 16);
    const uint32_t b_row  = (uint32_t)(nw * 32 + (lane & 7) + ((lane >> 4) << 3));
    const uint32_t b_colb = (uint32_t)(((lane >> 3) & 1) * 16);

    // ---- next-chunk build state ----
    int4   idn;
    float4 wtn;
    const float* xcn = xb;
    uint32_t nbase = sb;

    auto set_meta = [&](int chunk, uint32_t base) {
        const int tap = chunk >> 2;
        const int c0  = (chunk & 3) * 64;
        const int off = (b * NTAP + tap) * HW + p0 + am;
        idn = g_idx[off];
        wtn = g_wt[off];
        xcn = xb + (size_t)(c0 + aq * 16) * HW;
        nbase = base;
    };
    auto a_load8 = [&](int g, float* v) {
        const float* xp0 = xcn + (size_t)(2 * g) * HW;
        const float* xp1 = xp0 + HW;
        v[0] = __ldg(xp0 + idn.x); v[1] = __ldg(xp0 + idn.y);
        v[2] = __ldg(xp0 + idn.z); v[3] = __ldg(xp0 + idn.w);
        v[4] = __ldg(xp1 + idn.x); v[5] = __ldg(xp1 + idn.y);
        v[6] = __ldg(xp1 + idn.z); v[7] = __ldg(xp1 + idn.w);
    };
    auto a_finish = [&](int g, const float* v) {
        const float v0 = wtn.x * v[0] + wtn.y * v[1] + wtn.z * v[2] + wtn.w * v[3];
        const float v1 = wtn.x * v[4] + wtn.y * v[5] + wtn.z * v[6] + wtn.w * v[7];
        uint32_t lo2, hi2 = pack_bf16x2(v0, v1, lo2);
        const uint32_t bo = (uint32_t)(am * ROWB + (aq * 16 + 2 * g) * 2);
        asm volatile("st.shared.b32 [%0], %1;" :: "r"(nbase + SM_AHI + bo), "r"(hi2) : "memory");
        asm volatile("st.shared.b32 [%0], %1;" :: "r"(nbase + SM_ALO + bo), "r"(lo2) : "memory");
    };
    auto b_async = [&](int chunk, uint32_t base) {
        const int tap = chunk >> 2;
        const int c0  = (chunk & 3) * 64;
#pragma unroll
        for (int q2 = 0; q2 < 4; q2++) {
            const int v2 = t + 512 * q2;
            const int n = v2 >> 3, vw = v2 & 7;
            const size_t gofs = (size_t)n * KTOT + tap * 256 + c0 + vw * 8;
            const uint32_t bo = (uint32_t)(n * ROWB + vw * 16);
            cpasync16(base + SM_BHI + bo, g_bh + gofs);
            cpasync16(base + SM_BLO + bo, g_bl + gofs);
        }
        CP_COMMIT();
    };

    auto pass1_step = [&](uint32_t base, int s) {
        const uint32_t Ah = base + SM_AHI;
        const uint32_t Bh = base + SM_BHI, Bl = base + SM_BLO;
        uint32_t af[4][4];
#pragma unroll
        for (int mi = 0; mi < 4; mi++)
            ldm_x4(af[mi], Ah + (a_row + mi * 16) * ROWB + a_colb + s * 32);
        uint32_t bhf[4][2], blf[4][2];
#pragma unroll
        for (int np = 0; np < 2; np++) {
            uint32_t r[4];
            ldm_x4(r, Bh + (b_row + np * 16) * ROWB + b_colb + s * 32);
            bhf[np * 2][0] = r[0]; bhf[np * 2][1] = r[1];
            bhf[np * 2 + 1][0] = r[2]; bhf[np * 2 + 1][1] = r[3];
            ldm_x4(r, Bl + (b_row + np * 16) * ROWB + b_colb + s * 32);
            blf[np * 2][0] = r[0]; blf[np * 2][1] = r[1];
            blf[np * 2 + 1][0] = r[2]; blf[np * 2 + 1][1] = r[3];
        }
#pragma unroll
        for (int mi = 0; mi < 4; mi++)
#pragma unroll
            for (int ni = 0; ni < 4; ni++) {
                mma_bf16(acc[mi][ni], af[mi], bhf[ni]);
                mma_bf16(acc[mi][ni], af[mi], blf[ni]);
            }
    };
    auto pass2_step = [&](uint32_t base, int s) {
        const uint32_t Al = base + SM_ALO;
        const uint32_t Bh = base + SM_BHI;
        uint32_t af[4][4];
#pragma unroll
        for (int mi = 0; mi < 4; mi++)
            ldm_x4(af[mi], Al + (a_row + mi * 16) * ROWB + a_colb + s * 32);
        uint32_t bhf[4][2];
#pragma unroll
        for (int np = 0; np < 2; np++) {
            uint32_t r[4];
            ldm_x4(r, Bh + (b_row + np * 16) * ROWB + b_colb + s * 32);
            bhf[np * 2][0] = r[0]; bhf[np * 2][1] = r[1];
            bhf[np * 2 + 1][0] = r[2]; bhf[np * 2 + 1][1] = r[3];
        }
#pragma unroll
        for (int mi = 0; mi < 4; mi++)
#pragma unroll
            for (int ni = 0; ni < 4; ni++)
                mma_bf16(acc[mi][ni], af[mi], bhf[ni]);
    };

    // ---- prologue: build chunk 0 ----
    b_async(0, sb);
    set_meta(0, sb);
    {
        float v[8];
#pragma unroll
        for (int g = 0; g < 8; g++) { a_load8(g, v); a_finish(g, v); }
    }
    CP_WAIT0();
    __syncthreads();

    // ---- pipelined K loop ----
    for (int chunk = 0; chunk < NCHUNK; chunk++) {
        const uint32_t cur = sb + (uint32_t)(chunk & 1) * BUF_BYTES;
        const bool hn = (chunk + 1 < NCHUNK);
        if (hn) {
            const uint32_t nxt = sb + (uint32_t)((chunk + 1) & 1) * BUF_BYTES;
            b_async(chunk + 1, nxt);
            set_meta(chunk + 1, nxt);
        }
        float v[8];
        pass1_step(cur, 0);
        if (hn) a_load8(0, v);
        pass1_step(cur, 1);
        if (hn) { a_finish(0, v); a_load8(1, v); }
        pass1_step(cur, 2);
        if (hn) { a_finish(1, v); a_load8(2, v); }
        pass1_step(cur, 3);
        if (hn) { a_finish(2, v); a_load8(3, v); }
        pass2_step(cur, 0);
        if (hn) { a_finish(3, v); a_load8(4, v); }
        pass2_step(cur, 1);
        if (hn) { a_finish(4, v); a_load8(5, v); }
        pass2_step(cur, 2);
        if (hn) { a_finish(5, v); a_load8(6, v); }
        pass2_step(cur, 3);
        if (hn) { a_finish(6, v); a_load8(7, v); a_finish(7, v); }
        if (hn) CP_WAIT0();
        __syncthreads();
    }

    // ---- epilogue ----
    float* ob = out + (size_t)b * COUT * HW + p0;
    const int mbase = mw * 64 + (lane >> 2);
    const int nbase2 = nw * 32 + (lane & 3) * 2;
#pragma unroll
    for (int mi = 0; mi < 4; mi++) {
#pragma unroll
        for (int ni = 0; ni < 4; ni++) {
            const int m = mbase + mi * 16;
            const int n = nbase2 + ni * 8;
            ob[(size_t)n * HW + m]           = acc[mi][ni][0];
            ob[(size_t)(n + 1) * HW + m]     = acc[mi][ni][1];
            ob[(size_t)n * HW + m + 8]       = acc[mi][ni][2];
            ob[(size_t)(n + 1) * HW + m + 8] = acc[mi][ni][3];
        }
    }
}

// ---------------------------------------------------------------------------
extern "C" void kernel_launch(void* const* d_in, const int* in_sizes, int n_in,
                              void* d_out, int out_size)
{
    (void)in_sizes; (void)n_in; (void)out_size;
    const float* x      = (const float*)d_in[0];
    const float* w_off  = (const float*)d_in[1];
    const float* b_off  = (const float*)d_in[2];
    const float* w_conv = (const float*)d_in[3];
    float* out = (float*)d_out;

    cudaFuncSetAttribute(mma_kernel,
                         cudaFuncAttributeMaxDynamicSharedMemorySize, SMEM_TOTAL);
    cudaFuncSetAttribute(offset_mma_kernel,
                         cudaFuncAttributeMaxDynamicSharedMemorySize, OSMEM_TOTAL);

    prepack_kernel<<<((COUT + 32) * KTOT + 255) / 256, 256>>>(w_conv, w_off);
    offset_mma_kernel<<<128, 256, OSMEM_TOTAL>>>(x, b_off);
    mma_kernel<<<128, 512, SMEM_TOTAL>>>(x, out);
}